// round 5
// baseline (speedup 1.0000x reference)
#include <cuda_runtime.h>
#include <cuda_fp16.h>
#include <math_constants.h>

#define NN   50000
#define NE   800000
#define NET  (NE + NN)          // 850000 edges incl. self loops
#define FIN  128
#define FHID 128
#define FOUT 64
#define NEG  0.2f

// ---------------- scratch (static device globals; no allocation) ----------------
__device__ float  g_h1[NN * FHID];      // 25.6 MB  (fp32 h, layer1 — alpha reads)
__device__ float  g_acc1[NN * FHID];    // 25.6 MB  (layer1 output / layer2 input)
__device__ float  g_h2[NN * FOUT];      // 12.8 MB
__device__ __half g_h1h[NN * FHID];     // 12.8 MB  (fp16 h, layer1 — gather reads)
__device__ __half g_h2h[NN * FOUT];     //  6.4 MB
__device__ float  g_as[NN];
__device__ float  g_ad[NN];
__device__ int    g_cnt[NN];
__device__ int    g_off[NN + 1];
__device__ int    g_cur[NN];
__device__ int    g_srcA[NET];
__device__ int2   g_sw[NET];            // packed {src, __float_as_int(w)}

// ================= f32x2 packed-FMA helpers (sm_100+) =================
__device__ __forceinline__ unsigned long long pack2(float lo, float hi) {
    unsigned long long r;
    asm("mov.b64 %0, {%1, %2};" : "=l"(r) : "f"(lo), "f"(hi));
    return r;
}
__device__ __forceinline__ void ffma2(unsigned long long& d,
                                      unsigned long long a,
                                      unsigned long long b) {
    asm("fma.rn.f32x2 %0, %1, %2, %0;" : "+l"(d) : "l"(a), "l"(b));
}
__device__ __forceinline__ float2 unpack2(unsigned long long v) {
    float2 f;
    asm("mov.b64 {%0, %1}, %2;" : "=f"(f.x), "=f"(f.y) : "l"(v));
    return f;
}

// ====== GEMM: C[M,BN] = A[M,128] @ B[128,BN]; writes fp32 C and fp16 C16 =======
template<int BN>
__global__ void __launch_bounds__(256) gemm2_k(const float* __restrict__ A,
                                               const float* __restrict__ B,
                                               float* __restrict__ C,
                                               __half* __restrict__ C16, int M) {
    constexpr int K = 128, BM = 128, BK = 16;
    constexpr int TM = 8, TN = BN / 16;         // 8x8 (BN=128) or 8x4 (BN=64)
    constexpr int NP = TN / 2;                  // f32x2 pairs per row
    __shared__ float As[BK][BM + 4];            // transposed A tile, padded
    __shared__ float Bs[BK][BN];

    const int tid  = threadIdx.x;
    const int tx   = tid & 15;                  // col group (16)
    const int ty   = tid >> 4;                  // row group (16)
    const int row0 = blockIdx.x * BM;

    unsigned long long acc[TM][NP];
#pragma unroll
    for (int m = 0; m < TM; m++)
#pragma unroll
        for (int n = 0; n < NP; n++) acc[m][n] = 0ull;

    const float4* A4 = (const float4*)A;
    const float4* B4 = (const float4*)B;

    for (int kc = 0; kc < K; kc += BK) {
#pragma unroll
        for (int it = 0; it < 2; it++) {
            int i  = tid + it * 256;            // 512 float4 total
            int r  = i >> 2;
            int kg = i & 3;
            float4 v = make_float4(0.f, 0.f, 0.f, 0.f);
            if (row0 + r < M)
                v = A4[(size_t)(row0 + r) * (K / 4) + (kc >> 2) + kg];
            As[kg * 4 + 0][r] = v.x;
            As[kg * 4 + 1][r] = v.y;
            As[kg * 4 + 2][r] = v.z;
            As[kg * 4 + 3][r] = v.w;
        }
#pragma unroll
        for (int i = tid; i < BK * BN / 4; i += 256) {
            int r = i / (BN / 4);
            int c = i % (BN / 4);
            *(float4*)&Bs[r][c * 4] = B4[(size_t)(kc + r) * (BN / 4) + c];
        }
        __syncthreads();

#pragma unroll
        for (int k = 0; k < BK; k++) {
            float4 a0 = *(const float4*)&As[k][ty * TM];
            float4 a1 = *(const float4*)&As[k][ty * TM + 4];
            float a[TM] = {a0.x, a0.y, a0.z, a0.w, a1.x, a1.y, a1.z, a1.w};
            unsigned long long bp[NP];
            float4 b0 = *(const float4*)&Bs[k][tx * TN];
            bp[0] = pack2(b0.x, b0.y);
            bp[1] = pack2(b0.z, b0.w);
            if constexpr (TN == 8) {
                float4 b1 = *(const float4*)&Bs[k][tx * TN + 4];
                bp[2] = pack2(b1.x, b1.y);
                bp[3] = pack2(b1.z, b1.w);
            }
#pragma unroll
            for (int m = 0; m < TM; m++) {
                unsigned long long ap = pack2(a[m], a[m]);
#pragma unroll
                for (int n = 0; n < NP; n++) ffma2(acc[m][n], ap, bp[n]);
            }
        }
        __syncthreads();
    }

#pragma unroll
    for (int m = 0; m < TM; m++) {
        int r = row0 + ty * TM + m;
        if (r < M) {
            float*  cp  = &C[(size_t)r * BN + tx * TN];
            __half* hp  = &C16[(size_t)r * BN + tx * TN];
            float2 p[NP];
#pragma unroll
            for (int n = 0; n < NP; n++) p[n] = unpack2(acc[m][n]);
#pragma unroll
            for (int n = 0; n < NP; n += 2)
                *(float4*)(cp + n * 2) = make_float4(p[n].x, p[n].y, p[n + 1].x, p[n + 1].y);
            // fp16 copy
            unsigned int hh[NP];
#pragma unroll
            for (int n = 0; n < NP; n++) {
                __half2 h2v = __float22half2_rn(p[n]);
                hh[n] = *(unsigned int*)&h2v;
            }
            if constexpr (NP == 4)
                *(uint4*)hp = make_uint4(hh[0], hh[1], hh[2], hh[3]);
            else
                *(uint2*)hp = make_uint2(hh[0], hh[1]);
        }
    }
}

// ---------------- per-node attention logits ----------------
template<int F>
__global__ void alpha_k(const float* __restrict__ h,
                        const float* __restrict__ a_s,
                        const float* __restrict__ a_d,
                        float* __restrict__ as_out,
                        float* __restrict__ ad_out) {
    int warp = (blockIdx.x * blockDim.x + threadIdx.x) >> 5;
    int lane = threadIdx.x & 31;
    if (warp >= NN) return;
    float ss = 0.f, sd = 0.f;
#pragma unroll
    for (int f = lane; f < F; f += 32) {
        float hv = h[(size_t)warp * F + f];
        ss += hv * a_s[f];
        sd += hv * a_d[f];
    }
#pragma unroll
    for (int o = 16; o; o >>= 1) {
        ss += __shfl_down_sync(0xffffffffu, ss, o);
        sd += __shfl_down_sync(0xffffffffu, sd, o);
    }
    if (lane == 0) { as_out[warp] = ss; ad_out[warp] = sd; }
}

// ================= CSR build (dst-sorted adjacency) =================
__global__ void hist_k(const int* __restrict__ ei, int* __restrict__ cnt) {
    int idx = blockIdx.x * blockDim.x + threadIdx.x;
    if (idx >= NE) return;
    atomicAdd(&cnt[ei[NE + idx]], 1);
}

// single-block scan: off[i+1] = prefix-sum of (cnt[i]+1); 1024 thr, 4 elem/thr
__global__ void __launch_bounds__(1024) scan_k(const int* __restrict__ cnt,
                                               int* __restrict__ off) {
    __shared__ int wsum[32];
    const int tid  = threadIdx.x;
    const int wid  = tid >> 5;
    const int lane = tid & 31;
    int carry = 0;
    if (tid == 0) off[0] = 0;
    for (int base = 0; base < NN; base += 4096) {
        int i0 = base + tid * 4;
        int v0 = 0, v1 = 0, v2 = 0, v3 = 0;
        if (i0 + 3 < NN) {
            int4 c = *(const int4*)&cnt[i0];
            v0 = c.x + 1; v1 = c.y + 1; v2 = c.z + 1; v3 = c.w + 1;
        } else {
            if (i0 + 0 < NN) v0 = cnt[i0 + 0] + 1;
            if (i0 + 1 < NN) v1 = cnt[i0 + 1] + 1;
            if (i0 + 2 < NN) v2 = cnt[i0 + 2] + 1;
            if (i0 + 3 < NN) v3 = cnt[i0 + 3] + 1;
        }
        v1 += v0; v2 += v1; v3 += v2;
        int t = v3;
        int incl = t;
#pragma unroll
        for (int o = 1; o < 32; o <<= 1) {
            int n = __shfl_up_sync(0xffffffffu, incl, o);
            if (lane >= o) incl += n;
        }
        if (lane == 31) wsum[wid] = incl;
        __syncthreads();
        if (wid == 0) {
            int s = wsum[lane];
#pragma unroll
            for (int o = 1; o < 32; o <<= 1) {
                int n = __shfl_up_sync(0xffffffffu, s, o);
                if (lane >= o) s += n;
            }
            wsum[lane] = s;
        }
        __syncthreads();
        int prefix = carry + (wid ? wsum[wid - 1] : 0) + (incl - t);
        if (i0 + 0 < NN) off[i0 + 1] = prefix + v0;
        if (i0 + 1 < NN) off[i0 + 2] = prefix + v1;
        if (i0 + 2 < NN) off[i0 + 3] = prefix + v2;
        if (i0 + 3 < NN) off[i0 + 4] = prefix + v3;
        carry += wsum[31];
        __syncthreads();
    }
}

// place self loop at slot off[g]; cursor starts after it
__global__ void cur_k(const int* __restrict__ off, int* __restrict__ cur,
                      int* __restrict__ srcA) {
    int g = blockIdx.x * blockDim.x + threadIdx.x;
    if (g >= NN) return;
    int o = off[g];
    cur[g] = o + 1;
    srcA[o] = g;
}

__global__ void scatter_k(const int* __restrict__ ei, int* __restrict__ cur,
                          int* __restrict__ srcA) {
    int idx = blockIdx.x * blockDim.x + threadIdx.x;
    if (idx >= NE) return;
    int s = ei[idx];
    int d = ei[NE + idx];
    int p = atomicAdd(&cur[d], 1);
    srcA[p] = s;
}

// ============ precompute packed (src, w=exp(leaky(as[s]+ad[d]))) per edge ======
__global__ void wexp_k(const int* __restrict__ off, const int* __restrict__ srcA,
                       const float* __restrict__ as, const float* __restrict__ ad,
                       int2* __restrict__ sw) {
    int node = (blockIdx.x * blockDim.x + threadIdx.x) >> 5;
    int lane = threadIdx.x & 31;
    if (node >= NN) return;
    int beg = off[node], end = off[node + 1];
    float adn = ad[node];
    for (int k = beg + lane; k < end; k += 32) {
        int s = srcA[k];
        float e = as[s] + adn;
        e = e > 0.f ? e : NEG * e;
        sw[k] = make_int2(s, __float_as_int(__expf(e)));   // no max-shift: |e| small
    }
}

// ======== fused gather+softmax+aggregate, fp16 payload, F=128 (warp/node) ======
template<bool RELU>
__global__ void __launch_bounds__(256) agg128_k(
    const __half* __restrict__ h16, const int* __restrict__ off,
    const int2* __restrict__ sw, const float* __restrict__ bias,
    float* __restrict__ out) {
    int node = (blockIdx.x * blockDim.x + threadIdx.x) >> 5;
    int lane = threadIdx.x & 31;
    if (node >= NN) return;
    int beg = off[node], end = off[node + 1];

    const uint2* H = (const uint2*)h16;     // 32 uint2 (4 halves) per row
    float a0 = 0.f, a1 = 0.f, a2 = 0.f, a3 = 0.f, den = 0.f;

    int k = beg;
    for (; k + 4 <= end; k += 4) {
        int2 p0 = sw[k], p1 = sw[k + 1], p2 = sw[k + 2], p3 = sw[k + 3];
        uint2 q0 = H[(size_t)p0.x * 32 + lane];
        uint2 q1 = H[(size_t)p1.x * 32 + lane];
        uint2 q2 = H[(size_t)p2.x * 32 + lane];
        uint2 q3 = H[(size_t)p3.x * 32 + lane];
        float w0 = __int_as_float(p0.y), w1 = __int_as_float(p1.y);
        float w2 = __int_as_float(p2.y), w3 = __int_as_float(p3.y);
        den += (w0 + w1) + (w2 + w3);
        float2 f;
        f = __half22float2(*(__half2*)&q0.x); a0 += w0 * f.x; a1 += w0 * f.y;
        f = __half22float2(*(__half2*)&q0.y); a2 += w0 * f.x; a3 += w0 * f.y;
        f = __half22float2(*(__half2*)&q1.x); a0 += w1 * f.x; a1 += w1 * f.y;
        f = __half22float2(*(__half2*)&q1.y); a2 += w1 * f.x; a3 += w1 * f.y;
        f = __half22float2(*(__half2*)&q2.x); a0 += w2 * f.x; a1 += w2 * f.y;
        f = __half22float2(*(__half2*)&q2.y); a2 += w2 * f.x; a3 += w2 * f.y;
        f = __half22float2(*(__half2*)&q3.x); a0 += w3 * f.x; a1 += w3 * f.y;
        f = __half22float2(*(__half2*)&q3.y); a2 += w3 * f.x; a3 += w3 * f.y;
    }
    for (; k < end; k++) {
        int2 p = sw[k];
        float w = __int_as_float(p.y);
        den += w;
        uint2 q = H[(size_t)p.x * 32 + lane];
        float2 f;
        f = __half22float2(*(__half2*)&q.x); a0 += w * f.x; a1 += w * f.y;
        f = __half22float2(*(__half2*)&q.y); a2 += w * f.x; a3 += w * f.y;
    }

    float inv = 1.f / den;                  // den identical across lanes
    float4 b = ((const float4*)bias)[lane];
    float4 o = make_float4(a0 * inv + b.x, a1 * inv + b.y,
                           a2 * inv + b.z, a3 * inv + b.w);
    if (RELU) {
        o.x = o.x > 0.f ? o.x : 0.f;
        o.y = o.y > 0.f ? o.y : 0.f;
        o.z = o.z > 0.f ? o.z : 0.f;
        o.w = o.w > 0.f ? o.w : 0.f;
    }
    ((float4*)out)[(size_t)node * 32 + lane] = o;
}

// ======== same for F=64 ========
template<bool RELU>
__global__ void __launch_bounds__(256) agg64_k(
    const __half* __restrict__ h16, const int* __restrict__ off,
    const int2* __restrict__ sw, const float* __restrict__ bias,
    float* __restrict__ out) {
    int node = (blockIdx.x * blockDim.x + threadIdx.x) >> 5;
    int lane = threadIdx.x & 31;
    if (node >= NN) return;
    int beg = off[node], end = off[node + 1];

    const unsigned int* H = (const unsigned int*)h16;   // 32 half2 per row
    float a0 = 0.f, a1 = 0.f, den = 0.f;

    int k = beg;
    for (; k + 4 <= end; k += 4) {
        int2 p0 = sw[k], p1 = sw[k + 1], p2 = sw[k + 2], p3 = sw[k + 3];
        unsigned int q0 = H[(size_t)p0.x * 32 + lane];
        unsigned int q1 = H[(size_t)p1.x * 32 + lane];
        unsigned int q2 = H[(size_t)p2.x * 32 + lane];
        unsigned int q3 = H[(size_t)p3.x * 32 + lane];
        float w0 = __int_as_float(p0.y), w1 = __int_as_float(p1.y);
        float w2 = __int_as_float(p2.y), w3 = __int_as_float(p3.y);
        den += (w0 + w1) + (w2 + w3);
        float2 f;
        f = __half22float2(*(__half2*)&q0); a0 += w0 * f.x; a1 += w0 * f.y;
        f = __half22float2(*(__half2*)&q1); a0 += w1 * f.x; a1 += w1 * f.y;
        f = __half22float2(*(__half2*)&q2); a0 += w2 * f.x; a1 += w2 * f.y;
        f = __half22float2(*(__half2*)&q3); a0 += w3 * f.x; a1 += w3 * f.y;
    }
    for (; k < end; k++) {
        int2 p = sw[k];
        float w = __int_as_float(p.y);
        den += w;
        unsigned int q = H[(size_t)p.x * 32 + lane];
        float2 f = __half22float2(*(__half2*)&q);
        a0 += w * f.x; a1 += w * f.y;
    }

    float inv = 1.f / den;
    float2 b = ((const float2*)bias)[lane];
    float2 o = make_float2(a0 * inv + b.x, a1 * inv + b.y);
    if (RELU) {
        o.x = o.x > 0.f ? o.x : 0.f;
        o.y = o.y > 0.f ? o.y : 0.f;
    }
    ((float2*)out)[(size_t)node * 32 + lane] = o;
}

// ---------------- launch ----------------
extern "C" void kernel_launch(void* const* d_in, const int* in_sizes, int n_in,
                              void* d_out, int out_size) {
    const float* x   = (const float*)d_in[0];
    const int*   ei  = (const int*)d_in[1];
    const float* W1  = (const float*)d_in[2];
    const float* a1s = (const float*)d_in[3];
    const float* a1d = (const float*)d_in[4];
    const float* b1  = (const float*)d_in[5];
    const float* W2  = (const float*)d_in[6];
    const float* a2s = (const float*)d_in[7];
    const float* a2d = (const float*)d_in[8];
    const float* b2  = (const float*)d_in[9];
    float* out = (float*)d_out;

    float *h1, *acc1, *h2, *as, *ad;
    __half *h1h, *h2h;
    int *cnt, *off, *cur, *srcA;
    int2* sw;
    cudaGetSymbolAddress((void**)&h1,   g_h1);
    cudaGetSymbolAddress((void**)&acc1, g_acc1);
    cudaGetSymbolAddress((void**)&h2,   g_h2);
    cudaGetSymbolAddress((void**)&h1h,  g_h1h);
    cudaGetSymbolAddress((void**)&h2h,  g_h2h);
    cudaGetSymbolAddress((void**)&as,   g_as);
    cudaGetSymbolAddress((void**)&ad,   g_ad);
    cudaGetSymbolAddress((void**)&cnt,  g_cnt);
    cudaGetSymbolAddress((void**)&off,  g_off);
    cudaGetSymbolAddress((void**)&cur,  g_cur);
    cudaGetSymbolAddress((void**)&srcA, g_srcA);
    cudaGetSymbolAddress((void**)&sw,   g_sw);

    const int T = 256;

    // ---- CSR build (shared by both layers) ----
    cudaMemsetAsync(cnt, 0, NN * sizeof(int));
    hist_k<<<(NE + T - 1) / T, T>>>(ei, cnt);
    scan_k<<<1, 1024>>>(cnt, off);
    cur_k<<<(NN + T - 1) / T, T>>>(off, cur, srcA);
    scatter_k<<<(NE + T - 1) / T, T>>>(ei, cur, srcA);

    // ---- layer 1 (F=128) ----
    gemm2_k<FHID><<<(NN + 127) / 128, T>>>(x, W1, h1, h1h, NN);
    alpha_k<FHID><<<(NN * 32 + T - 1) / T, T>>>(h1, a1s, a1d, as, ad);
    wexp_k<<<(NN * 32 + T - 1) / T, T>>>(off, srcA, as, ad, sw);
    agg128_k<true><<<(NN * 32 + T - 1) / T, T>>>(h1h, off, sw, b1, acc1);

    // ---- layer 2 (F=64) ----
    gemm2_k<FOUT><<<(NN + 127) / 128, T>>>(acc1, W2, h2, h2h, NN);
    alpha_k<FOUT><<<(NN * 32 + T - 1) / T, T>>>(h2, a2s, a2d, as, ad);
    wexp_k<<<(NN * 32 + T - 1) / T, T>>>(off, srcA, as, ad, sw);
    agg64_k<false><<<(NN * 32 + T - 1) / T, T>>>(h2h, off, sw, b2, out);
}

// round 6
// speedup vs baseline: 1.1418x; 1.1418x over previous
#include <cuda_runtime.h>
#include <cuda_fp16.h>
#include <math_constants.h>

#define NN   50000
#define NE   800000
#define NET  (NE + NN)          // 850000 edges incl. self loops
#define FIN  128
#define FHID 128
#define FOUT 64
#define NEG  0.2f

// ---------------- scratch (static device globals; no allocation) ----------------
__device__ float  g_h1[NN * FHID];      // fp32 h layer1 (alpha reads)
__device__ float  g_acc1[NN * FHID];    // layer1 out / layer2 in
__device__ float  g_h2[NN * FOUT];
__device__ __half g_h1h[NN * FHID];     // fp16 h layer1 (gather reads)
__device__ __half g_h2h[NN * FOUT];
__device__ float  g_as[NN];
__device__ float  g_ad[NN];
__device__ int    g_cnt[NN];
__device__ int    g_off[NN + 1];
__device__ int    g_cur[NN];
__device__ int    g_srcA[NET];

// ================= f32x2 packed-FMA helpers (sm_100+) =================
__device__ __forceinline__ unsigned long long pack2(float lo, float hi) {
    unsigned long long r;
    asm("mov.b64 %0, {%1, %2};" : "=l"(r) : "f"(lo), "f"(hi));
    return r;
}
__device__ __forceinline__ void ffma2(unsigned long long& d,
                                      unsigned long long a,
                                      unsigned long long b) {
    asm("fma.rn.f32x2 %0, %1, %2, %0;" : "+l"(d) : "l"(a), "l"(b));
}
__device__ __forceinline__ float2 unpack2(unsigned long long v) {
    float2 f;
    asm("mov.b64 {%0, %1}, %2;" : "=f"(f.x), "=f"(f.y) : "l"(v));
    return f;
}

// ====== GEMM: C[M,BN] = A[M,128] @ B[128,BN]; writes fp32 C and fp16 C16 =======
template<int BN>
__global__ void __launch_bounds__(256) gemm2_k(const float* __restrict__ A,
                                               const float* __restrict__ B,
                                               float* __restrict__ C,
                                               __half* __restrict__ C16, int M) {
    constexpr int K = 128, BM = 128, BK = 16;
    constexpr int TM = 8, TN = BN / 16;
    constexpr int NP = TN / 2;
    __shared__ float As[BK][BM + 4];
    __shared__ float Bs[BK][BN];

    const int tid  = threadIdx.x;
    const int tx   = tid & 15;
    const int ty   = tid >> 4;
    const int row0 = blockIdx.x * BM;

    unsigned long long acc[TM][NP];
#pragma unroll
    for (int m = 0; m < TM; m++)
#pragma unroll
        for (int n = 0; n < NP; n++) acc[m][n] = 0ull;

    const float4* A4 = (const float4*)A;
    const float4* B4 = (const float4*)B;

    for (int kc = 0; kc < K; kc += BK) {
#pragma unroll
        for (int it = 0; it < 2; it++) {
            int i  = tid + it * 256;
            int r  = i >> 2;
            int kg = i & 3;
            float4 v = make_float4(0.f, 0.f, 0.f, 0.f);
            if (row0 + r < M)
                v = A4[(size_t)(row0 + r) * (K / 4) + (kc >> 2) + kg];
            As[kg * 4 + 0][r] = v.x;
            As[kg * 4 + 1][r] = v.y;
            As[kg * 4 + 2][r] = v.z;
            As[kg * 4 + 3][r] = v.w;
        }
#pragma unroll
        for (int i = tid; i < BK * BN / 4; i += 256) {
            int r = i / (BN / 4);
            int c = i % (BN / 4);
            *(float4*)&Bs[r][c * 4] = B4[(size_t)(kc + r) * (BN / 4) + c];
        }
        __syncthreads();

#pragma unroll
        for (int k = 0; k < BK; k++) {
            float4 a0 = *(const float4*)&As[k][ty * TM];
            float4 a1 = *(const float4*)&As[k][ty * TM + 4];
            float a[TM] = {a0.x, a0.y, a0.z, a0.w, a1.x, a1.y, a1.z, a1.w};
            unsigned long long bp[NP];
            float4 b0 = *(const float4*)&Bs[k][tx * TN];
            bp[0] = pack2(b0.x, b0.y);
            bp[1] = pack2(b0.z, b0.w);
            if constexpr (TN == 8) {
                float4 b1 = *(const float4*)&Bs[k][tx * TN + 4];
                bp[2] = pack2(b1.x, b1.y);
                bp[3] = pack2(b1.z, b1.w);
            }
#pragma unroll
            for (int m = 0; m < TM; m++) {
                unsigned long long ap = pack2(a[m], a[m]);
#pragma unroll
                for (int n = 0; n < NP; n++) ffma2(acc[m][n], ap, bp[n]);
            }
        }
        __syncthreads();
    }

#pragma unroll
    for (int m = 0; m < TM; m++) {
        int r = row0 + ty * TM + m;
        if (r < M) {
            float*  cp = &C[(size_t)r * BN + tx * TN];
            __half* hp = &C16[(size_t)r * BN + tx * TN];
            float2 p[NP];
#pragma unroll
            for (int n = 0; n < NP; n++) p[n] = unpack2(acc[m][n]);
#pragma unroll
            for (int n = 0; n < NP; n += 2)
                *(float4*)(cp + n * 2) = make_float4(p[n].x, p[n].y, p[n + 1].x, p[n + 1].y);
            unsigned int hh[NP];
#pragma unroll
            for (int n = 0; n < NP; n++) {
                __half2 h2v = __float22half2_rn(p[n]);
                hh[n] = *(unsigned int*)&h2v;
            }
            if constexpr (NP == 4)
                *(uint4*)hp = make_uint4(hh[0], hh[1], hh[2], hh[3]);
            else
                *(uint2*)hp = make_uint2(hh[0], hh[1]);
        }
    }
}

// ---------------- per-node attention logits ----------------
template<int F>
__global__ void alpha_k(const float* __restrict__ h,
                        const float* __restrict__ a_s,
                        const float* __restrict__ a_d,
                        float* __restrict__ as_out,
                        float* __restrict__ ad_out) {
    int warp = (blockIdx.x * blockDim.x + threadIdx.x) >> 5;
    int lane = threadIdx.x & 31;
    if (warp >= NN) return;
    float ss = 0.f, sd = 0.f;
#pragma unroll
    for (int f = lane; f < F; f += 32) {
        float hv = h[(size_t)warp * F + f];
        ss += hv * a_s[f];
        sd += hv * a_d[f];
    }
#pragma unroll
    for (int o = 16; o; o >>= 1) {
        ss += __shfl_down_sync(0xffffffffu, ss, o);
        sd += __shfl_down_sync(0xffffffffu, sd, o);
    }
    if (lane == 0) { as_out[warp] = ss; ad_out[warp] = sd; }
}

// ================= CSR build (dst-sorted adjacency) =================
// 4 edges per thread for MLP=4 on the atomics
__global__ void hist_k(const int* __restrict__ ei, int* __restrict__ cnt) {
    int t = blockIdx.x * blockDim.x + threadIdx.x;
    int idx = t * 4;
    if (idx >= NE) return;
    int4 d = *(const int4*)&ei[NE + idx];
    atomicAdd(&cnt[d.x], 1);
    atomicAdd(&cnt[d.y], 1);
    atomicAdd(&cnt[d.z], 1);
    atomicAdd(&cnt[d.w], 1);
}

// single-block scan: off[i+1] = prefix-sum of (cnt[i]+1)
__global__ void __launch_bounds__(1024) scan_k(const int* __restrict__ cnt,
                                               int* __restrict__ off) {
    __shared__ int wsum[32];
    const int tid  = threadIdx.x;
    const int wid  = tid >> 5;
    const int lane = tid & 31;
    int carry = 0;
    if (tid == 0) off[0] = 0;
    for (int base = 0; base < NN; base += 4096) {
        int i0 = base + tid * 4;
        int v0 = 0, v1 = 0, v2 = 0, v3 = 0;
        if (i0 + 3 < NN) {
            int4 c = *(const int4*)&cnt[i0];
            v0 = c.x + 1; v1 = c.y + 1; v2 = c.z + 1; v3 = c.w + 1;
        } else {
            if (i0 + 0 < NN) v0 = cnt[i0 + 0] + 1;
            if (i0 + 1 < NN) v1 = cnt[i0 + 1] + 1;
            if (i0 + 2 < NN) v2 = cnt[i0 + 2] + 1;
            if (i0 + 3 < NN) v3 = cnt[i0 + 3] + 1;
        }
        v1 += v0; v2 += v1; v3 += v2;
        int t = v3;
        int incl = t;
#pragma unroll
        for (int o = 1; o < 32; o <<= 1) {
            int n = __shfl_up_sync(0xffffffffu, incl, o);
            if (lane >= o) incl += n;
        }
        if (lane == 31) wsum[wid] = incl;
        __syncthreads();
        if (wid == 0) {
            int s = wsum[lane];
#pragma unroll
            for (int o = 1; o < 32; o <<= 1) {
                int n = __shfl_up_sync(0xffffffffu, s, o);
                if (lane >= o) s += n;
            }
            wsum[lane] = s;
        }
        __syncthreads();
        int prefix = carry + (wid ? wsum[wid - 1] : 0) + (incl - t);
        if (i0 + 0 < NN) off[i0 + 1] = prefix + v0;
        if (i0 + 1 < NN) off[i0 + 2] = prefix + v1;
        if (i0 + 2 < NN) off[i0 + 3] = prefix + v2;
        if (i0 + 3 < NN) off[i0 + 4] = prefix + v3;
        carry += wsum[31];
        __syncthreads();
    }
}

__global__ void cur_k(const int* __restrict__ off, int* __restrict__ cur,
                      int* __restrict__ srcA) {
    int g = blockIdx.x * blockDim.x + threadIdx.x;
    if (g >= NN) return;
    int o = off[g];
    cur[g] = o + 1;           // self loop occupies slot off[g]
    srcA[o] = g;
}

__global__ void scatter_k(const int* __restrict__ ei, int* __restrict__ cur,
                          int* __restrict__ srcA) {
    int t = blockIdx.x * blockDim.x + threadIdx.x;
    int idx = t * 4;
    if (idx >= NE) return;
    int4 s = *(const int4*)&ei[idx];
    int4 d = *(const int4*)&ei[NE + idx];
    int p0 = atomicAdd(&cur[d.x], 1);
    int p1 = atomicAdd(&cur[d.y], 1);
    int p2 = atomicAdd(&cur[d.z], 1);
    int p3 = atomicAdd(&cur[d.w], 1);
    srcA[p0] = s.x;
    srcA[p1] = s.y;
    srcA[p2] = s.z;
    srcA[p3] = s.w;
}

// ======== fused gather+softmax+aggregate, fp16 payload, F=128 (warp/node) ======
template<bool RELU>
__global__ void __launch_bounds__(256) agg128_k(
    const __half* __restrict__ h16,
    const float* __restrict__ as, const float* __restrict__ ad,
    const int* __restrict__ off, const int* __restrict__ srcA,
    const float* __restrict__ bias, float* __restrict__ out) {
    int node = (blockIdx.x * blockDim.x + threadIdx.x) >> 5;
    int lane = threadIdx.x & 31;
    if (node >= NN) return;
    int beg = off[node], end = off[node + 1];
    float adn = ad[node];

    const uint2* H = (const uint2*)h16;     // 32 uint2 (4 halves) per row
    float a0 = 0.f, a1 = 0.f, a2 = 0.f, a3 = 0.f, den = 0.f;

    for (int base = beg; base < end; base += 32) {
        int k = base + lane;
        int s = 0;
        float w = 0.f;
        if (k < end) {
            s = srcA[k];
            float e = as[s] + adn;
            e = e > 0.f ? e : NEG * e;
            w = __expf(e);                  // no max-shift: softmax invariant, |e| small
        }
        den += w;
        int cnt = min(32, end - base);
        int j = 0;
        for (; j + 4 <= cnt; j += 4) {
            int   s0 = __shfl_sync(0xffffffffu, s, j);
            int   s1 = __shfl_sync(0xffffffffu, s, j + 1);
            int   s2 = __shfl_sync(0xffffffffu, s, j + 2);
            int   s3 = __shfl_sync(0xffffffffu, s, j + 3);
            float w0 = __shfl_sync(0xffffffffu, w, j);
            float w1 = __shfl_sync(0xffffffffu, w, j + 1);
            float w2 = __shfl_sync(0xffffffffu, w, j + 2);
            float w3 = __shfl_sync(0xffffffffu, w, j + 3);
            uint2 q0 = H[(size_t)s0 * 32 + lane];
            uint2 q1 = H[(size_t)s1 * 32 + lane];
            uint2 q2 = H[(size_t)s2 * 32 + lane];
            uint2 q3 = H[(size_t)s3 * 32 + lane];
            float2 f;
            f = __half22float2(*(__half2*)&q0.x); a0 += w0 * f.x; a1 += w0 * f.y;
            f = __half22float2(*(__half2*)&q0.y); a2 += w0 * f.x; a3 += w0 * f.y;
            f = __half22float2(*(__half2*)&q1.x); a0 += w1 * f.x; a1 += w1 * f.y;
            f = __half22float2(*(__half2*)&q1.y); a2 += w1 * f.x; a3 += w1 * f.y;
            f = __half22float2(*(__half2*)&q2.x); a0 += w2 * f.x; a1 += w2 * f.y;
            f = __half22float2(*(__half2*)&q2.y); a2 += w2 * f.x; a3 += w2 * f.y;
            f = __half22float2(*(__half2*)&q3.x); a0 += w3 * f.x; a1 += w3 * f.y;
            f = __half22float2(*(__half2*)&q3.y); a2 += w3 * f.x; a3 += w3 * f.y;
        }
        for (; j < cnt; j++) {
            int   sj = __shfl_sync(0xffffffffu, s, j);
            float wj = __shfl_sync(0xffffffffu, w, j);
            uint2 q = H[(size_t)sj * 32 + lane];
            float2 f;
            f = __half22float2(*(__half2*)&q.x); a0 += wj * f.x; a1 += wj * f.y;
            f = __half22float2(*(__half2*)&q.y); a2 += wj * f.x; a3 += wj * f.y;
        }
    }

#pragma unroll
    for (int o = 16; o; o >>= 1) den += __shfl_xor_sync(0xffffffffu, den, o);
    float inv = 1.f / den;
    float4 b = ((const float4*)bias)[lane];
    float4 o4 = make_float4(a0 * inv + b.x, a1 * inv + b.y,
                            a2 * inv + b.z, a3 * inv + b.w);
    if (RELU) {
        o4.x = o4.x > 0.f ? o4.x : 0.f;
        o4.y = o4.y > 0.f ? o4.y : 0.f;
        o4.z = o4.z > 0.f ? o4.z : 0.f;
        o4.w = o4.w > 0.f ? o4.w : 0.f;
    }
    ((float4*)out)[(size_t)node * 32 + lane] = o4;
}

// ======== same for F=64 ========
template<bool RELU>
__global__ void __launch_bounds__(256) agg64_k(
    const __half* __restrict__ h16,
    const float* __restrict__ as, const float* __restrict__ ad,
    const int* __restrict__ off, const int* __restrict__ srcA,
    const float* __restrict__ bias, float* __restrict__ out) {
    int node = (blockIdx.x * blockDim.x + threadIdx.x) >> 5;
    int lane = threadIdx.x & 31;
    if (node >= NN) return;
    int beg = off[node], end = off[node + 1];
    float adn = ad[node];

    const unsigned int* H = (const unsigned int*)h16;   // 32 half2 per row
    float a0 = 0.f, a1 = 0.f, den = 0.f;

    for (int base = beg; base < end; base += 32) {
        int k = base + lane;
        int s = 0;
        float w = 0.f;
        if (k < end) {
            s = srcA[k];
            float e = as[s] + adn;
            e = e > 0.f ? e : NEG * e;
            w = __expf(e);
        }
        den += w;
        int cnt = min(32, end - base);
        int j = 0;
        for (; j + 4 <= cnt; j += 4) {
            int   s0 = __shfl_sync(0xffffffffu, s, j);
            int   s1 = __shfl_sync(0xffffffffu, s, j + 1);
            int   s2 = __shfl_sync(0xffffffffu, s, j + 2);
            int   s3 = __shfl_sync(0xffffffffu, s, j + 3);
            float w0 = __shfl_sync(0xffffffffu, w, j);
            float w1 = __shfl_sync(0xffffffffu, w, j + 1);
            float w2 = __shfl_sync(0xffffffffu, w, j + 2);
            float w3 = __shfl_sync(0xffffffffu, w, j + 3);
            unsigned int q0 = H[(size_t)s0 * 32 + lane];
            unsigned int q1 = H[(size_t)s1 * 32 + lane];
            unsigned int q2 = H[(size_t)s2 * 32 + lane];
            unsigned int q3 = H[(size_t)s3 * 32 + lane];
            float2 f;
            f = __half22float2(*(__half2*)&q0); a0 += w0 * f.x; a1 += w0 * f.y;
            f = __half22float2(*(__half2*)&q1); a0 += w1 * f.x; a1 += w1 * f.y;
            f = __half22float2(*(__half2*)&q2); a0 += w2 * f.x; a1 += w2 * f.y;
            f = __half22float2(*(__half2*)&q3); a0 += w3 * f.x; a1 += w3 * f.y;
        }
        for (; j < cnt; j++) {
            int   sj = __shfl_sync(0xffffffffu, s, j);
            float wj = __shfl_sync(0xffffffffu, w, j);
            unsigned int q = H[(size_t)sj * 32 + lane];
            float2 f = __half22float2(*(__half2*)&q);
            a0 += wj * f.x; a1 += wj * f.y;
        }
    }

#pragma unroll
    for (int o = 16; o; o >>= 1) den += __shfl_xor_sync(0xffffffffu, den, o);
    float inv = 1.f / den;
    float2 b = ((const float2*)bias)[lane];
    float2 o2 = make_float2(a0 * inv + b.x, a1 * inv + b.y);
    if (RELU) {
        o2.x = o2.x > 0.f ? o2.x : 0.f;
        o2.y = o2.y > 0.f ? o2.y : 0.f;
    }
    ((float2*)out)[(size_t)node * 32 + lane] = o2;
}

// ---------------- launch ----------------
extern "C" void kernel_launch(void* const* d_in, const int* in_sizes, int n_in,
                              void* d_out, int out_size) {
    const float* x   = (const float*)d_in[0];
    const int*   ei  = (const int*)d_in[1];
    const float* W1  = (const float*)d_in[2];
    const float* a1s = (const float*)d_in[3];
    const float* a1d = (const float*)d_in[4];
    const float* b1  = (const float*)d_in[5];
    const float* W2  = (const float*)d_in[6];
    const float* a2s = (const float*)d_in[7];
    const float* a2d = (const float*)d_in[8];
    const float* b2  = (const float*)d_in[9];
    float* out = (float*)d_out;

    float *h1, *acc1, *h2, *as, *ad;
    __half *h1h, *h2h;
    int *cnt, *off, *cur, *srcA;
    cudaGetSymbolAddress((void**)&h1,   g_h1);
    cudaGetSymbolAddress((void**)&acc1, g_acc1);
    cudaGetSymbolAddress((void**)&h2,   g_h2);
    cudaGetSymbolAddress((void**)&h1h,  g_h1h);
    cudaGetSymbolAddress((void**)&h2h,  g_h2h);
    cudaGetSymbolAddress((void**)&as,   g_as);
    cudaGetSymbolAddress((void**)&ad,   g_ad);
    cudaGetSymbolAddress((void**)&cnt,  g_cnt);
    cudaGetSymbolAddress((void**)&off,  g_off);
    cudaGetSymbolAddress((void**)&cur,  g_cur);
    cudaGetSymbolAddress((void**)&srcA, g_srcA);

    const int T = 256;

    // Fork: CSR build (stream s2) runs concurrently with gemm1+alpha1 (stream 0)
    cudaStream_t s2;
    cudaStreamCreateWithFlags(&s2, cudaStreamNonBlocking);
    cudaEvent_t evFork, evJoin;
    cudaEventCreateWithFlags(&evFork, cudaEventDisableTiming);
    cudaEventCreateWithFlags(&evJoin, cudaEventDisableTiming);

    cudaEventRecord(evFork, 0);
    cudaStreamWaitEvent(s2, evFork, 0);

    // ---- CSR build on s2 ----
    cudaMemsetAsync(cnt, 0, NN * sizeof(int), s2);
    hist_k<<<(NE / 4 + T - 1) / T, T, 0, s2>>>(ei, cnt);
    scan_k<<<1, 1024, 0, s2>>>(cnt, off);
    cur_k<<<(NN + T - 1) / T, T, 0, s2>>>(off, cur, srcA);
    scatter_k<<<(NE / 4 + T - 1) / T, T, 0, s2>>>(ei, cur, srcA);
    cudaEventRecord(evJoin, s2);

    // ---- layer 1 dense part on stream 0 (concurrent with CSR) ----
    gemm2_k<FHID><<<(NN + 127) / 128, T>>>(x, W1, h1, h1h, NN);
    alpha_k<FHID><<<(NN * 32 + T - 1) / T, T>>>(h1, a1s, a1d, as, ad);

    cudaStreamWaitEvent(0, evJoin, 0);

    // ---- layer 1 aggregate ----
    agg128_k<true><<<(NN * 32 + T - 1) / T, T>>>(h1h, as, ad, off, srcA, b1, acc1);

    // ---- layer 2 (F=64) ----
    gemm2_k<FOUT><<<(NN + 127) / 128, T>>>(acc1, W2, h2, h2h, NN);
    alpha_k<FOUT><<<(NN * 32 + T - 1) / T, T>>>(h2, a2s, a2d, as, ad);
    agg64_k<false><<<(NN * 32 + T - 1) / T, T>>>(h2h, as, ad, off, srcA, b2, out);

    cudaEventDestroy(evFork);
    cudaEventDestroy(evJoin);
    cudaStreamDestroy(s2);
}

// round 7
// speedup vs baseline: 1.5345x; 1.3439x over previous
#include <cuda_runtime.h>
#include <cuda_fp16.h>
#include <math_constants.h>

#define NN   50000
#define NE   800000
#define NET  (NE + NN)          // 850000 edges incl. self loops
#define FIN  128
#define FHID 128
#define FOUT 64
#define NEG  0.2f

// ---------------- scratch (static device globals; no allocation) ----------------
__device__ __half g_h1h[NN * FHID];     // fp16 h layer1
__device__ __half g_acc1h[NN * FHID];   // fp16 layer1 out / layer2 in
__device__ __half g_h2h[NN * FOUT];     // fp16 h layer2
__device__ __half g_w1t[FHID * FIN];    // W1^T fp16  [n][k]
__device__ __half g_w2t[FOUT * FHID];   // W2^T fp16  [n][k]
__device__ float  g_as[NN];
__device__ float  g_ad[NN];
__device__ int    g_cnt[NN];
__device__ int    g_off[NN + 1];
__device__ int    g_rank[NE];
__device__ int    g_srcA[NET];

// ================= mma.m16n8k16 fp16 -> fp32 =================
__device__ __forceinline__ void mma16816(float* c, const unsigned* a,
                                         unsigned b0, unsigned b1) {
    asm volatile(
        "mma.sync.aligned.m16n8k16.row.col.f32.f16.f16.f32 "
        "{%0,%1,%2,%3}, {%4,%5,%6,%7}, {%8,%9}, {%0,%1,%2,%3};\n"
        : "+f"(c[0]), "+f"(c[1]), "+f"(c[2]), "+f"(c[3])
        : "r"(a[0]), "r"(a[1]), "r"(a[2]), "r"(a[3]), "r"(b0), "r"(b1));
}

// ---- convert W1, W2 to fp16 transposed [n][k] ----
__global__ void convW_k(const float* __restrict__ W1, const float* __restrict__ W2,
                        __half* __restrict__ Wt1, __half* __restrict__ Wt2) {
    int i = blockIdx.x * blockDim.x + threadIdx.x;
    if (i < FIN * FHID) {
        int k = i / FHID, n = i % FHID;
        Wt1[n * FIN + k] = __float2half(W1[i]);
    }
    if (i < FHID * FOUT) {
        int k = i / FOUT, n = i % FOUT;
        Wt2[n * FHID + k] = __float2half(W2[i]);
    }
}

// ====== HGEMM: C16[M,BN] = A[M,128] @ Bt^T ; A fp32 (AF16=0) or fp16 (AF16=1) ===
template<int BN, bool AF16>
__global__ void __launch_bounds__(256) hgemm_k(const void* __restrict__ Aptr,
                                               const __half* __restrict__ Bt,  // [BN][128]
                                               __half* __restrict__ C16, int M) {
    constexpr int K = 128, BM = 128, BK = 64;
    constexpr int MT = (BN == 128) ? 2 : 1;     // m16 frags per warp
    __shared__ __half Ah[BM][BK + 8];
    __shared__ __half Bs[BN][BK + 8];

    const int tid  = threadIdx.x;
    const int wid  = tid >> 5;
    const int lane = tid & 31;
    const int gr   = lane >> 2;
    const int tig  = lane & 3;
    const int row0 = blockIdx.x * BM;

    int warpRow, warpCol;
    if (BN == 128) { warpRow = (wid >> 1) * 32; warpCol = (wid & 1) * 64; }
    else           { warpRow = wid * 16;        warpCol = 0; }

    float acc[MT][8][4];
#pragma unroll
    for (int mi = 0; mi < MT; mi++)
#pragma unroll
        for (int ni = 0; ni < 8; ni++)
#pragma unroll
            for (int j = 0; j < 4; j++) acc[mi][ni][j] = 0.f;

    for (int kc = 0; kc < K; kc += BK) {
        if (AF16) {
#pragma unroll
            for (int i = tid; i < BM * BK / 8; i += 256) {
                int r = i / (BK / 8), c8 = i % (BK / 8);
                uint4 v = make_uint4(0, 0, 0, 0);
                if (row0 + r < M)
                    v = *(const uint4*)((const __half*)Aptr + (size_t)(row0 + r) * K + kc + c8 * 8);
                *(uint4*)&Ah[r][c8 * 8] = v;
            }
        } else {
#pragma unroll
            for (int i = tid; i < BM * BK / 4; i += 256) {
                int r = i / (BK / 4), c4 = i % (BK / 4);
                float4 v = make_float4(0.f, 0.f, 0.f, 0.f);
                if (row0 + r < M)
                    v = *(const float4*)((const float*)Aptr + (size_t)(row0 + r) * K + kc + c4 * 4);
                __half2 h0 = __floats2half2_rn(v.x, v.y);
                __half2 h1 = __floats2half2_rn(v.z, v.w);
                *(uint2*)&Ah[r][c4 * 4] = make_uint2(*(unsigned*)&h0, *(unsigned*)&h1);
            }
        }
#pragma unroll
        for (int i = tid; i < BN * BK / 8; i += 256) {
            int n = i / (BK / 8), c8 = i % (BK / 8);
            *(uint4*)&Bs[n][c8 * 8] = *(const uint4*)(Bt + (size_t)n * K + kc + c8 * 8);
        }
        __syncthreads();

#pragma unroll
        for (int kk = 0; kk < BK; kk += 16) {
            unsigned a[MT][4];
#pragma unroll
            for (int mi = 0; mi < MT; mi++) {
                int r = warpRow + mi * 16 + gr;
                a[mi][0] = *(unsigned*)&Ah[r][kk + tig * 2];
                a[mi][1] = *(unsigned*)&Ah[r + 8][kk + tig * 2];
                a[mi][2] = *(unsigned*)&Ah[r][kk + tig * 2 + 8];
                a[mi][3] = *(unsigned*)&Ah[r + 8][kk + tig * 2 + 8];
            }
#pragma unroll
            for (int ni = 0; ni < 8; ni++) {
                int n = warpCol + ni * 8 + gr;
                unsigned b0 = *(unsigned*)&Bs[n][kk + tig * 2];
                unsigned b1 = *(unsigned*)&Bs[n][kk + tig * 2 + 8];
#pragma unroll
                for (int mi = 0; mi < MT; mi++) mma16816(acc[mi][ni], a[mi], b0, b1);
            }
        }
        __syncthreads();
    }

#pragma unroll
    for (int mi = 0; mi < MT; mi++)
#pragma unroll
        for (int ni = 0; ni < 8; ni++) {
            int r = row0 + warpRow + mi * 16 + gr;
            int c = warpCol + ni * 8 + tig * 2;
            __half2 lo = __floats2half2_rn(acc[mi][ni][0], acc[mi][ni][1]);
            __half2 hi = __floats2half2_rn(acc[mi][ni][2], acc[mi][ni][3]);
            if (r < M)     *(__half2*)&C16[(size_t)r * BN + c] = lo;
            if (r + 8 < M) *(__half2*)&C16[(size_t)(r + 8) * BN + c] = hi;
        }
}

// ---------------- per-node attention logits from fp16 h ----------------
template<int F>
__global__ void alpha16_k(const __half* __restrict__ h16,
                          const float* __restrict__ a_s,
                          const float* __restrict__ a_d,
                          float* __restrict__ as_out,
                          float* __restrict__ ad_out) {
    int warp = (blockIdx.x * blockDim.x + threadIdx.x) >> 5;
    int lane = threadIdx.x & 31;
    if (warp >= NN) return;
    float ss = 0.f, sd = 0.f;
    if constexpr (F == 128) {
        uint2 q = ((const uint2*)h16)[(size_t)warp * 32 + lane];
        float2 f0 = __half22float2(*(__half2*)&q.x);
        float2 f1 = __half22float2(*(__half2*)&q.y);
        float4 av = ((const float4*)a_s)[lane];
        float4 dv = ((const float4*)a_d)[lane];
        ss = f0.x * av.x + f0.y * av.y + f1.x * av.z + f1.y * av.w;
        sd = f0.x * dv.x + f0.y * dv.y + f1.x * dv.z + f1.y * dv.w;
    } else {
        unsigned q = ((const unsigned*)h16)[(size_t)warp * 32 + lane];
        float2 f = __half22float2(*(__half2*)&q);
        float2 av = ((const float2*)a_s)[lane];
        float2 dv = ((const float2*)a_d)[lane];
        ss = f.x * av.x + f.y * av.y;
        sd = f.x * dv.x + f.y * dv.y;
    }
#pragma unroll
    for (int o = 16; o; o >>= 1) {
        ss += __shfl_down_sync(0xffffffffu, ss, o);
        sd += __shfl_down_sync(0xffffffffu, sd, o);
    }
    if (lane == 0) { as_out[warp] = ss; ad_out[warp] = sd; }
}

// ================= CSR build (dst-sorted adjacency) =================
// hist also records each edge's rank within its dst bucket (atomic return value)
__global__ void hist_k(const int* __restrict__ ei, int* __restrict__ cnt,
                       int* __restrict__ rank) {
    int t = blockIdx.x * blockDim.x + threadIdx.x;
    int idx = t * 4;
    if (idx >= NE) return;
    int4 d = *(const int4*)&ei[NE + idx];
    int r0 = atomicAdd(&cnt[d.x], 1);
    int r1 = atomicAdd(&cnt[d.y], 1);
    int r2 = atomicAdd(&cnt[d.z], 1);
    int r3 = atomicAdd(&cnt[d.w], 1);
    *(int4*)&rank[idx] = make_int4(r0, r1, r2, r3);
}

// single-block scan: off[i+1] = prefix-sum of (cnt[i]+1)
__global__ void __launch_bounds__(1024) scan_k(const int* __restrict__ cnt,
                                               int* __restrict__ off) {
    __shared__ int wsum[32];
    const int tid  = threadIdx.x;
    const int wid  = tid >> 5;
    const int lane = tid & 31;
    int carry = 0;
    if (tid == 0) off[0] = 0;
    for (int base = 0; base < NN; base += 4096) {
        int i0 = base + tid * 4;
        int v0 = 0, v1 = 0, v2 = 0, v3 = 0;
        if (i0 + 3 < NN) {
            int4 c = *(const int4*)&cnt[i0];
            v0 = c.x + 1; v1 = c.y + 1; v2 = c.z + 1; v3 = c.w + 1;
        } else {
            if (i0 + 0 < NN) v0 = cnt[i0 + 0] + 1;
            if (i0 + 1 < NN) v1 = cnt[i0 + 1] + 1;
            if (i0 + 2 < NN) v2 = cnt[i0 + 2] + 1;
            if (i0 + 3 < NN) v3 = cnt[i0 + 3] + 1;
        }
        v1 += v0; v2 += v1; v3 += v2;
        int t = v3;
        int incl = t;
#pragma unroll
        for (int o = 1; o < 32; o <<= 1) {
            int n = __shfl_up_sync(0xffffffffu, incl, o);
            if (lane >= o) incl += n;
        }
        if (lane == 31) wsum[wid] = incl;
        __syncthreads();
        if (wid == 0) {
            int s = wsum[lane];
#pragma unroll
            for (int o = 1; o < 32; o <<= 1) {
                int n = __shfl_up_sync(0xffffffffu, s, o);
                if (lane >= o) s += n;
            }
            wsum[lane] = s;
        }
        __syncthreads();
        int prefix = carry + (wid ? wsum[wid - 1] : 0) + (incl - t);
        if (i0 + 0 < NN) off[i0 + 1] = prefix + v0;
        if (i0 + 1 < NN) off[i0 + 2] = prefix + v1;
        if (i0 + 2 < NN) off[i0 + 3] = prefix + v2;
        if (i0 + 3 < NN) off[i0 + 4] = prefix + v3;
        carry += wsum[31];
        __syncthreads();
    }
}

// self loop occupies slot off[g]
__global__ void self_k(const int* __restrict__ off, int* __restrict__ srcA) {
    int g = blockIdx.x * blockDim.x + threadIdx.x;
    if (g < NN) srcA[off[g]] = g;
}

// atomic-free scatter: position = off[dst] + 1 + rank
__global__ void scatter_k(const int* __restrict__ ei, const int* __restrict__ off,
                          const int* __restrict__ rank, int* __restrict__ srcA) {
    int t = blockIdx.x * blockDim.x + threadIdx.x;
    int idx = t * 4;
    if (idx >= NE) return;
    int4 s  = *(const int4*)&ei[idx];
    int4 d  = *(const int4*)&ei[NE + idx];
    int4 rk = *(const int4*)&rank[idx];
    srcA[off[d.x] + 1 + rk.x] = s.x;
    srcA[off[d.y] + 1 + rk.y] = s.y;
    srcA[off[d.z] + 1 + rk.z] = s.z;
    srcA[off[d.w] + 1 + rk.w] = s.w;
}

// ======== fused gather+softmax+aggregate, F=128, fp16 in, fp16 out (+relu) =====
__global__ void __launch_bounds__(256) agg128_k(
    const __half* __restrict__ h16,
    const float* __restrict__ as, const float* __restrict__ ad,
    const int* __restrict__ off, const int* __restrict__ srcA,
    const float* __restrict__ bias, __half* __restrict__ out16) {
    int node = (blockIdx.x * blockDim.x + threadIdx.x) >> 5;
    int lane = threadIdx.x & 31;
    if (node >= NN) return;
    int beg = off[node], end = off[node + 1];
    float adn = ad[node];

    const uint2* H = (const uint2*)h16;
    float a0 = 0.f, a1 = 0.f, a2 = 0.f, a3 = 0.f, den = 0.f;

    for (int base = beg; base < end; base += 32) {
        int k = base + lane;
        int s = 0;
        float w = 0.f;
        if (k < end) {
            s = srcA[k];
            float e = as[s] + adn;
            e = e > 0.f ? e : NEG * e;
            w = __expf(e);                  // no max-shift: softmax invariant, |e| small
        }
        den += w;
        int cnt = min(32, end - base);
        int j = 0;
        for (; j + 4 <= cnt; j += 4) {
            int   s0 = __shfl_sync(0xffffffffu, s, j);
            int   s1 = __shfl_sync(0xffffffffu, s, j + 1);
            int   s2 = __shfl_sync(0xffffffffu, s, j + 2);
            int   s3 = __shfl_sync(0xffffffffu, s, j + 3);
            float w0 = __shfl_sync(0xffffffffu, w, j);
            float w1 = __shfl_sync(0xffffffffu, w, j + 1);
            float w2 = __shfl_sync(0xffffffffu, w, j + 2);
            float w3 = __shfl_sync(0xffffffffu, w, j + 3);
            uint2 q0 = H[(size_t)s0 * 32 + lane];
            uint2 q1 = H[(size_t)s1 * 32 + lane];
            uint2 q2 = H[(size_t)s2 * 32 + lane];
            uint2 q3 = H[(size_t)s3 * 32 + lane];
            float2 f;
            f = __half22float2(*(__half2*)&q0.x); a0 += w0 * f.x; a1 += w0 * f.y;
            f = __half22float2(*(__half2*)&q0.y); a2 += w0 * f.x; a3 += w0 * f.y;
            f = __half22float2(*(__half2*)&q1.x); a0 += w1 * f.x; a1 += w1 * f.y;
            f = __half22float2(*(__half2*)&q1.y); a2 += w1 * f.x; a3 += w1 * f.y;
            f = __half22float2(*(__half2*)&q2.x); a0 += w2 * f.x; a1 += w2 * f.y;
            f = __half22float2(*(__half2*)&q2.y); a2 += w2 * f.x; a3 += w2 * f.y;
            f = __half22float2(*(__half2*)&q3.x); a0 += w3 * f.x; a1 += w3 * f.y;
            f = __half22float2(*(__half2*)&q3.y); a2 += w3 * f.x; a3 += w3 * f.y;
        }
        for (; j < cnt; j++) {
            int   sj = __shfl_sync(0xffffffffu, s, j);
            float wj = __shfl_sync(0xffffffffu, w, j);
            uint2 q = H[(size_t)sj * 32 + lane];
            float2 f;
            f = __half22float2(*(__half2*)&q.x); a0 += wj * f.x; a1 += wj * f.y;
            f = __half22float2(*(__half2*)&q.y); a2 += wj * f.x; a3 += wj * f.y;
        }
    }

#pragma unroll
    for (int o = 16; o; o >>= 1) den += __shfl_xor_sync(0xffffffffu, den, o);
    float inv = 1.f / den;
    float4 b = ((const float4*)bias)[lane];
    float o0 = a0 * inv + b.x, o1 = a1 * inv + b.y;
    float o2 = a2 * inv + b.z, o3 = a3 * inv + b.w;
    o0 = o0 > 0.f ? o0 : 0.f;
    o1 = o1 > 0.f ? o1 : 0.f;
    o2 = o2 > 0.f ? o2 : 0.f;
    o3 = o3 > 0.f ? o3 : 0.f;
    __half2 lo = __floats2half2_rn(o0, o1);
    __half2 hi = __floats2half2_rn(o2, o3);
    ((uint2*)out16)[(size_t)node * 32 + lane] = make_uint2(*(unsigned*)&lo, *(unsigned*)&hi);
}

// ======== F=64, fp16 in, fp32 out (final) ========
__global__ void __launch_bounds__(256) agg64_k(
    const __half* __restrict__ h16,
    const float* __restrict__ as, const float* __restrict__ ad,
    const int* __restrict__ off, const int* __restrict__ srcA,
    const float* __restrict__ bias, float* __restrict__ out) {
    int node = (blockIdx.x * blockDim.x + threadIdx.x) >> 5;
    int lane = threadIdx.x & 31;
    if (node >= NN) return;
    int beg = off[node], end = off[node + 1];
    float adn = ad[node];

    const unsigned int* H = (const unsigned int*)h16;
    float a0 = 0.f, a1 = 0.f, den = 0.f;

    for (int base = beg; base < end; base += 32) {
        int k = base + lane;
        int s = 0;
        float w = 0.f;
        if (k < end) {
            s = srcA[k];
            float e = as[s] + adn;
            e = e > 0.f ? e : NEG * e;
            w = __expf(e);
        }
        den += w;
        int cnt = min(32, end - base);
        int j = 0;
        for (; j + 4 <= cnt; j += 4) {
            int   s0 = __shfl_sync(0xffffffffu, s, j);
            int   s1 = __shfl_sync(0xffffffffu, s, j + 1);
            int   s2 = __shfl_sync(0xffffffffu, s, j + 2);
            int   s3 = __shfl_sync(0xffffffffu, s, j + 3);
            float w0 = __shfl_sync(0xffffffffu, w, j);
            float w1 = __shfl_sync(0xffffffffu, w, j + 1);
            float w2 = __shfl_sync(0xffffffffu, w, j + 2);
            float w3 = __shfl_sync(0xffffffffu, w, j + 3);
            unsigned int q0 = H[(size_t)s0 * 32 + lane];
            unsigned int q1 = H[(size_t)s1 * 32 + lane];
            unsigned int q2 = H[(size_t)s2 * 32 + lane];
            unsigned int q3 = H[(size_t)s3 * 32 + lane];
            float2 f;
            f = __half22float2(*(__half2*)&q0); a0 += w0 * f.x; a1 += w0 * f.y;
            f = __half22float2(*(__half2*)&q1); a0 += w1 * f.x; a1 += w1 * f.y;
            f = __half22float2(*(__half2*)&q2); a0 += w2 * f.x; a1 += w2 * f.y;
            f = __half22float2(*(__half2*)&q3); a0 += w3 * f.x; a1 += w3 * f.y;
        }
        for (; j < cnt; j++) {
            int   sj = __shfl_sync(0xffffffffu, s, j);
            float wj = __shfl_sync(0xffffffffu, w, j);
            unsigned int q = H[(size_t)sj * 32 + lane];
            float2 f = __half22float2(*(__half2*)&q);
            a0 += wj * f.x; a1 += wj * f.y;
        }
    }

#pragma unroll
    for (int o = 16; o; o >>= 1) den += __shfl_xor_sync(0xffffffffu, den, o);
    float inv = 1.f / den;
    float2 b = ((const float2*)bias)[lane];
    float2 o2 = make_float2(a0 * inv + b.x, a1 * inv + b.y);
    ((float2*)out)[(size_t)node * 32 + lane] = o2;
}

// ---------------- launch ----------------
extern "C" void kernel_launch(void* const* d_in, const int* in_sizes, int n_in,
                              void* d_out, int out_size) {
    const float* x   = (const float*)d_in[0];
    const int*   ei  = (const int*)d_in[1];
    const float* W1  = (const float*)d_in[2];
    const float* a1s = (const float*)d_in[3];
    const float* a1d = (const float*)d_in[4];
    const float* b1  = (const float*)d_in[5];
    const float* W2  = (const float*)d_in[6];
    const float* a2s = (const float*)d_in[7];
    const float* a2d = (const float*)d_in[8];
    const float* b2  = (const float*)d_in[9];
    float* out = (float*)d_out;

    __half *h1h, *acc1h, *h2h, *w1t, *w2t;
    float *as, *ad;
    int *cnt, *off, *rank, *srcA;
    cudaGetSymbolAddress((void**)&h1h,   g_h1h);
    cudaGetSymbolAddress((void**)&acc1h, g_acc1h);
    cudaGetSymbolAddress((void**)&h2h,   g_h2h);
    cudaGetSymbolAddress((void**)&w1t,   g_w1t);
    cudaGetSymbolAddress((void**)&w2t,   g_w2t);
    cudaGetSymbolAddress((void**)&as,    g_as);
    cudaGetSymbolAddress((void**)&ad,    g_ad);
    cudaGetSymbolAddress((void**)&cnt,   g_cnt);
    cudaGetSymbolAddress((void**)&off,   g_off);
    cudaGetSymbolAddress((void**)&rank,  g_rank);
    cudaGetSymbolAddress((void**)&srcA,  g_srcA);

    const int T = 256;

    // Fork: CSR build (s2) concurrent with convW + gemm1 + alpha1 (stream 0)
    cudaStream_t s2;
    cudaStreamCreateWithFlags(&s2, cudaStreamNonBlocking);
    cudaEvent_t evFork, evJoin;
    cudaEventCreateWithFlags(&evFork, cudaEventDisableTiming);
    cudaEventCreateWithFlags(&evJoin, cudaEventDisableTiming);

    cudaEventRecord(evFork, 0);
    cudaStreamWaitEvent(s2, evFork, 0);

    // ---- CSR build on s2 ----
    cudaMemsetAsync(cnt, 0, NN * sizeof(int), s2);
    hist_k<<<(NE / 4 + T - 1) / T, T, 0, s2>>>(ei, cnt, rank);
    scan_k<<<1, 1024, 0, s2>>>(cnt, off);
    self_k<<<(NN + T - 1) / T, T, 0, s2>>>(off, srcA);
    scatter_k<<<(NE / 4 + T - 1) / T, T, 0, s2>>>(ei, off, rank, srcA);
    cudaEventRecord(evJoin, s2);

    // ---- layer 1 dense part on stream 0 (concurrent with CSR) ----
    convW_k<<<(FIN * FHID + T - 1) / T, T>>>(W1, W2, w1t, w2t);
    hgemm_k<FHID, false><<<(NN + 127) / 128, T>>>(x, w1t, h1h, NN);
    alpha16_k<FHID><<<(NN * 32 + T - 1) / T, T>>>(h1h, a1s, a1d, as, ad);

    cudaStreamWaitEvent(0, evJoin, 0);

    // ---- layer 1 aggregate (fp16 out, relu) ----
    agg128_k<<<(NN * 32 + T - 1) / T, T>>>(h1h, as, ad, off, srcA, b1, acc1h);

    // ---- layer 2 ----
    hgemm_k<FOUT, true><<<(NN + 127) / 128, T>>>(acc1h, w2t, h2h, NN);
    alpha16_k<FOUT><<<(NN * 32 + T - 1) / T, T>>>(h2h, a2s, a2d, as, ad);
    agg64_k<<<(NN * 32 + T - 1) / T, T>>>(h2h, as, ad, off, srcA, b2, out);

    cudaEventDestroy(evFork);
    cudaEventDestroy(evJoin);
    cudaStreamDestroy(s2);
}